// round 5
// baseline (speedup 1.0000x reference)
#include <cuda_runtime.h>
#include <math.h>

#define BATCH 8
#define LC    2048
#define LQ    512
#define DIM   768

// Scratch: St[b][c][q]  (logits transposed so softmax axis q is contiguous)
__device__ float g_S[BATCH * LC * LQ];

// ---------------------------------------------------------------------------
// GEMM1: St[c,q] = sum_d C[c,d] * Q[q,d]     (both operands K-major, "NT")
// 128x128 block tile, K-step 8, 256 threads, 8x8 microtile.
// ---------------------------------------------------------------------------
__global__ __launch_bounds__(256, 2)
void gemm1_nt_kernel(const float* __restrict__ Cg,
                     const float* __restrict__ Qg,
                     float* __restrict__ Sg)
{
    const int b  = blockIdx.z;
    const int m0 = blockIdx.x * 128;   // c
    const int n0 = blockIdx.y * 128;   // q

    const float* A = Cg + (size_t)b * LC * DIM;   // [LC, DIM]
    const float* Bm = Qg + (size_t)b * LQ * DIM;  // [LQ, DIM]
    float* S = g_S ? Sg + (size_t)b * LC * LQ : nullptr;

    __shared__ float As[8][128];
    __shared__ float Bs[8][128];

    const int t   = threadIdx.x;
    const int tx  = t & 15;
    const int ty  = t >> 4;
    const int lrow = t >> 1;        // 0..127
    const int lseg = (t & 1) * 4;   // 0 or 4

    float acc[8][8];
#pragma unroll
    for (int i = 0; i < 8; i++)
#pragma unroll
        for (int j = 0; j < 8; j++) acc[i][j] = 0.f;

    for (int k0 = 0; k0 < DIM; k0 += 8) {
        // load A tile (128 rows x 8 k) -> As[k][m]
        float4 av = *reinterpret_cast<const float4*>(&A[(size_t)(m0 + lrow) * DIM + k0 + lseg]);
        As[lseg + 0][lrow] = av.x;
        As[lseg + 1][lrow] = av.y;
        As[lseg + 2][lrow] = av.z;
        As[lseg + 3][lrow] = av.w;
        // load B tile (128 rows x 8 k) -> Bs[k][n]
        float4 bv = *reinterpret_cast<const float4*>(&Bm[(size_t)(n0 + lrow) * DIM + k0 + lseg]);
        Bs[lseg + 0][lrow] = bv.x;
        Bs[lseg + 1][lrow] = bv.y;
        Bs[lseg + 2][lrow] = bv.z;
        Bs[lseg + 3][lrow] = bv.w;
        __syncthreads();

#pragma unroll
        for (int k = 0; k < 8; k++) {
            float a[8], bb[8];
            *reinterpret_cast<float4*>(&a[0])  = *reinterpret_cast<const float4*>(&As[k][ty * 4]);
            *reinterpret_cast<float4*>(&a[4])  = *reinterpret_cast<const float4*>(&As[k][64 + ty * 4]);
            *reinterpret_cast<float4*>(&bb[0]) = *reinterpret_cast<const float4*>(&Bs[k][tx * 4]);
            *reinterpret_cast<float4*>(&bb[4]) = *reinterpret_cast<const float4*>(&Bs[k][64 + tx * 4]);
#pragma unroll
            for (int i = 0; i < 8; i++)
#pragma unroll
                for (int j = 0; j < 8; j++) acc[i][j] = fmaf(a[i], bb[j], acc[i][j]);
        }
        __syncthreads();
    }

    // write back
#pragma unroll
    for (int i = 0; i < 8; i++) {
        int m = m0 + ((i < 4) ? (ty * 4 + i) : (64 + ty * 4 + i - 4));
#pragma unroll
        for (int jj = 0; jj < 2; jj++) {
            int n = n0 + ((jj == 0) ? (tx * 4) : (64 + tx * 4));
            float4 v = make_float4(acc[i][jj * 4 + 0], acc[i][jj * 4 + 1],
                                   acc[i][jj * 4 + 2], acc[i][jj * 4 + 3]);
            *reinterpret_cast<float4*>(&S[(size_t)m * LQ + n]) = v;
        }
    }
}

// ---------------------------------------------------------------------------
// Softmax along q (contiguous rows of length 512). One warp per row.
// ---------------------------------------------------------------------------
__global__ __launch_bounds__(256)
void softmax_rows_kernel(float* __restrict__ S)
{
    const int row  = blockIdx.x * 8 + (threadIdx.x >> 5);
    const int lane = threadIdx.x & 31;
    float* p = S + (size_t)row * LQ;

    float v[16];
    float mx = -INFINITY;
#pragma unroll
    for (int i = 0; i < 16; i++) {
        v[i] = p[lane + i * 32];
        mx = fmaxf(mx, v[i]);
    }
#pragma unroll
    for (int o = 16; o > 0; o >>= 1) mx = fmaxf(mx, __shfl_xor_sync(0xffffffffu, mx, o));

    float sum = 0.f;
#pragma unroll
    for (int i = 0; i < 16; i++) {
        v[i] = expf(v[i] - mx);
        sum += v[i];
    }
#pragma unroll
    for (int o = 16; o > 0; o >>= 1) sum += __shfl_xor_sync(0xffffffffu, sum, o);
    const float inv = 1.f / sum;
#pragma unroll
    for (int i = 0; i < 16; i++) p[lane + i * 32] = v[i] * inv;
}

// ---------------------------------------------------------------------------
// GEMM2 + gate: out[c,d] = C[c,d] * sum_q St[c,q] * Q[q,d]
// A = St (LC x LQ, K contiguous), B = Q (LQ x DIM, N contiguous) -> "NN"
// ---------------------------------------------------------------------------
__global__ __launch_bounds__(256, 2)
void gemm2_nn_gate_kernel(const float* __restrict__ Sg,
                          const float* __restrict__ Qg,
                          const float* __restrict__ Cg,
                          float* __restrict__ Og)
{
    const int b  = blockIdx.z;
    const int m0 = blockIdx.x * 128;   // c
    const int n0 = blockIdx.y * 128;   // d

    const float* A  = Sg + (size_t)b * LC * LQ;    // [LC, LQ]
    const float* Bm = Qg + (size_t)b * LQ * DIM;   // [LQ, DIM]
    const float* G  = Cg + (size_t)b * LC * DIM;   // gate
    float* O        = Og + (size_t)b * LC * DIM;

    __shared__ float As[8][128];
    __shared__ float Bs[8][128];

    const int t  = threadIdx.x;
    const int tx = t & 15;
    const int ty = t >> 4;
    const int lrow = t >> 1;
    const int lseg = (t & 1) * 4;
    const int bkrow = t >> 5;          // 0..7
    const int bcol  = (t & 31) * 4;    // 0..124

    float acc[8][8];
#pragma unroll
    for (int i = 0; i < 8; i++)
#pragma unroll
        for (int j = 0; j < 8; j++) acc[i][j] = 0.f;

    for (int k0 = 0; k0 < LQ; k0 += 8) {
        float4 av = *reinterpret_cast<const float4*>(&A[(size_t)(m0 + lrow) * LQ + k0 + lseg]);
        As[lseg + 0][lrow] = av.x;
        As[lseg + 1][lrow] = av.y;
        As[lseg + 2][lrow] = av.z;
        As[lseg + 3][lrow] = av.w;
        float4 bv = *reinterpret_cast<const float4*>(&Bm[(size_t)(k0 + bkrow) * DIM + n0 + bcol]);
        *reinterpret_cast<float4*>(&Bs[bkrow][bcol]) = bv;
        __syncthreads();

#pragma unroll
        for (int k = 0; k < 8; k++) {
            float a[8], bb[8];
            *reinterpret_cast<float4*>(&a[0])  = *reinterpret_cast<const float4*>(&As[k][ty * 4]);
            *reinterpret_cast<float4*>(&a[4])  = *reinterpret_cast<const float4*>(&As[k][64 + ty * 4]);
            *reinterpret_cast<float4*>(&bb[0]) = *reinterpret_cast<const float4*>(&Bs[k][tx * 4]);
            *reinterpret_cast<float4*>(&bb[4]) = *reinterpret_cast<const float4*>(&Bs[k][64 + tx * 4]);
#pragma unroll
            for (int i = 0; i < 8; i++)
#pragma unroll
                for (int j = 0; j < 8; j++) acc[i][j] = fmaf(a[i], bb[j], acc[i][j]);
        }
        __syncthreads();
    }

#pragma unroll
    for (int i = 0; i < 8; i++) {
        int m = m0 + ((i < 4) ? (ty * 4 + i) : (64 + ty * 4 + i - 4));
#pragma unroll
        for (int jj = 0; jj < 2; jj++) {
            int n = n0 + ((jj == 0) ? (tx * 4) : (64 + tx * 4));
            float4 g = *reinterpret_cast<const float4*>(&G[(size_t)m * DIM + n]);
            float4 v = make_float4(acc[i][jj * 4 + 0] * g.x, acc[i][jj * 4 + 1] * g.y,
                                   acc[i][jj * 4 + 2] * g.z, acc[i][jj * 4 + 3] * g.w);
            *reinterpret_cast<float4*>(&O[(size_t)m * DIM + n]) = v;
        }
    }
}

// ---------------------------------------------------------------------------
extern "C" void kernel_launch(void* const* d_in, const int* in_sizes, int n_in,
                              void* d_out, int out_size)
{
    // Identify inputs robustly by element count.
    const int ctx_elems = BATCH * LC * DIM;   // 12,582,912
    const float* ctx = nullptr;
    const float* qry = nullptr;
    if (in_sizes[0] == ctx_elems) {
        ctx = (const float*)d_in[0];
        qry = (const float*)d_in[1];
    } else {
        ctx = (const float*)d_in[1];
        qry = (const float*)d_in[0];
    }
    float* out = (float*)d_out;

    float* S = nullptr;
    cudaGetSymbolAddress((void**)&S, g_S);

    // GEMM1: St[b] = C[b] @ Q[b]^T  -> [LC, LQ]
    {
        dim3 grid(LC / 128, LQ / 128, BATCH);
        gemm1_nt_kernel<<<grid, 256>>>(ctx, qry, S);
    }
    // Softmax over q (contiguous rows)
    {
        dim3 grid(BATCH * LC / 8);
        softmax_rows_kernel<<<grid, 256>>>(S);
    }
    // GEMM2 + gate: out[b] = (St[b] @ Q[b]) * C[b]
    {
        dim3 grid(LC / 128, DIM / 128, BATCH);
        gemm2_nn_gate_kernel<<<grid, 256>>>(S, qry, ctx, out);
    }
    (void)n_in; (void)out_size;
}

// round 9
// speedup vs baseline: 2.2505x; 2.2505x over previous
#include <cuda_runtime.h>
#include <cuda_bf16.h>
#include <math.h>
#include <stdint.h>

#define BATCH 8
#define LC    2048
#define LQ    512
#define DIM   768

static constexpr size_t CE = (size_t)BATCH * LC * DIM;   // 12,582,912
static constexpr size_t QE = (size_t)BATCH * LQ * DIM;   //  3,145,728
static constexpr size_t SE = (size_t)BATCH * LC * LQ;    //  8,388,608

// ---- scratch layout (single __device__ blob; no allocation allowed) ----
static constexpr size_t OFF_S    = 0;                    // fp32 logits [B][LC][LQ]
static constexpr size_t OFF_CHI  = OFF_S   + SE * 4;
static constexpr size_t OFF_CLO  = OFF_CHI + CE * 2;
static constexpr size_t OFF_QHI  = OFF_CLO + CE * 2;
static constexpr size_t OFF_QLO  = OFF_QHI + QE * 2;
static constexpr size_t OFF_QTHI = OFF_QLO + QE * 2;     // Q transposed [B][DIM][LQ]
static constexpr size_t OFF_QTLO = OFF_QTHI + QE * 2;
static constexpr size_t OFF_SHI  = OFF_QTLO + QE * 2;    // softmax(alpha) split
static constexpr size_t OFF_SLO  = OFF_SHI + SE * 2;
static constexpr size_t SCRATCH_BYTES = OFF_SLO + SE * 2;

__device__ __align__(1024) unsigned char g_scratch[SCRATCH_BYTES];

// ======================= helpers (all plain sm_80+ PTX, no 'a' features) ===
__device__ __forceinline__ uint32_t smem_u32(const void* p) {
    uint32_t a;
    asm("{ .reg .u64 t; cvta.to.shared.u64 t, %1; cvt.u32.u64 %0, t; }" : "=r"(a) : "l"(p));
    return a;
}
__device__ __forceinline__ void cp_async16(uint32_t dst, const void* src) {
    asm volatile("cp.async.cg.shared.global [%0], [%1], 16;" :: "r"(dst), "l"(src) : "memory");
}
__device__ __forceinline__ void cp_commit() {
    asm volatile("cp.async.commit_group;" ::: "memory");
}
template <int N>
__device__ __forceinline__ void cp_wait() {
    asm volatile("cp.async.wait_group %0;" :: "n"(N) : "memory");
}
__device__ __forceinline__ void ldm_x4(uint32_t (&r)[4], uint32_t addr) {
    asm volatile("ldmatrix.sync.aligned.m8n8.x4.shared.b16 {%0,%1,%2,%3}, [%4];"
                 : "=r"(r[0]), "=r"(r[1]), "=r"(r[2]), "=r"(r[3]) : "r"(addr));
}
__device__ __forceinline__ void mma_16816(float (&c)[4], const uint32_t (&a)[4],
                                          uint32_t b0, uint32_t b1) {
    asm volatile("mma.sync.aligned.m16n8k16.row.col.f32.bf16.bf16.f32 "
                 "{%0,%1,%2,%3}, {%4,%5,%6,%7}, {%8,%9}, {%0,%1,%2,%3};"
                 : "+f"(c[0]), "+f"(c[1]), "+f"(c[2]), "+f"(c[3])
                 : "r"(a[0]), "r"(a[1]), "r"(a[2]), "r"(a[3]), "r"(b0), "r"(b1));
}
__device__ __forceinline__ uint32_t sw128(uint32_t off) {
    return off ^ ((off >> 3) & 0x70);   // Swizzle<3,4,3>: bits[6:4] ^= bits[9:7]
}

// ======================= HMMA GEMM (3-phase bf16 split) ====================
// D[M,N] = sum over phases p: Aph[p][M,K] (K-major) * Bph[p][N,K]^T (K-major)
// CTA tile 128x128, K-chunk 64 bf16 (128B rows, SW128), 3-stage cp.async.
static constexpr int STAGES = 3;
static constexpr int STAGE_BYTES = 32768;                 // A 16KB + B 16KB
static constexpr int SMEM_DYN_BYTES = STAGES * STAGE_BYTES;

template <int KDIM, int NTOT, int MTOT, bool GATE>
__global__ __launch_bounds__(256)
void mm_hmma_kernel(const __nv_bfloat16* __restrict__ A0, const __nv_bfloat16* __restrict__ A1,
                    const __nv_bfloat16* __restrict__ A2, const __nv_bfloat16* __restrict__ B0,
                    const __nv_bfloat16* __restrict__ B1, const __nv_bfloat16* __restrict__ B2,
                    const float* __restrict__ Gate, float* __restrict__ D)
{
    constexpr int CPP = KDIM / 64;   // chunks per phase
    constexpr int NCH = 3 * CPP;     // total chunks

    extern __shared__ unsigned char sm[];

    const int t   = threadIdx.x;
    const int wid = t >> 5;
    const int lid = t & 31;
    const int wm  = wid >> 1;        // 0..3  (M warp row, 32 rows each)
    const int wn  = wid & 1;         // 0..1  (N warp col, 64 cols each)

    const int b  = blockIdx.z;
    const int m0 = blockIdx.x * 128;
    const int n0 = blockIdx.y * 128;

    const size_t bA = (size_t)b * MTOT * KDIM;
    const size_t bB = (size_t)b * NTOT * KDIM;
    const __nv_bfloat16* APh[3] = { A0 + bA, A1 + bA, A2 + bA };
    const __nv_bfloat16* BPh[3] = { B0 + bB, B1 + bB, B2 + bB };

    // cp.async mapping: thread t covers rows (t>>3)+32j, 16B col (t&7)
    const int lr  = t >> 3;          // 0..31
    const int lc16 = (t & 7);        // 0..7
    const uint32_t sm_base = smem_u32(sm);

    auto load_chunk = [&](int c, int stage) {
        const int p  = c / CPP;
        const int kk = (c % CPP) * 64;
        const __nv_bfloat16* Ap = APh[p];
        const __nv_bfloat16* Bp = BPh[p];
        const uint32_t abase = sm_base + stage * STAGE_BYTES;
        const uint32_t bbase = abase + 16384;
#pragma unroll
        for (int j = 0; j < 4; j++) {
            const int row = lr + j * 32;
            const uint32_t sw = sw128((uint32_t)row * 128 + (uint32_t)lc16 * 16);
            cp_async16(abase + sw, Ap + (size_t)(m0 + row) * KDIM + kk + lc16 * 8);
            cp_async16(bbase + sw, Bp + (size_t)(n0 + row) * KDIM + kk + lc16 * 8);
        }
    };

    float acc[2][8][4];
#pragma unroll
    for (int i = 0; i < 2; i++)
#pragma unroll
        for (int j = 0; j < 8; j++)
#pragma unroll
            for (int k = 0; k < 4; k++) acc[i][j][k] = 0.f;

    // ldmatrix per-lane row/col (within a 16-row, 32-byte k-step window)
    const int arow = (lid & 7) + 8 * ((lid >> 3) & 1);   // A: m within 16
    const int acol = ((lid >> 4) & 1) * 16;              // A: k byte 0/16
    const int brow = (lid & 7) + 8 * ((lid >> 4) & 1);   // B: n within 16
    const int bcol = ((lid >> 3) & 1) * 16;              // B: k byte 0/16

    auto compute_chunk = [&](int stage) {
        const uint32_t abase = sm_base + stage * STAGE_BYTES;
        const uint32_t bbase = abase + 16384;
#pragma unroll
        for (int ks = 0; ks < 4; ks++) {
            uint32_t a[2][4];
#pragma unroll
            for (int mt = 0; mt < 2; mt++) {
                uint32_t off = (uint32_t)(wm * 32 + mt * 16 + arow) * 128 + ks * 32 + acol;
                ldm_x4(a[mt], abase + sw128(off));
            }
            uint32_t bf[4][4];
#pragma unroll
            for (int nb2 = 0; nb2 < 4; nb2++) {
                uint32_t off = (uint32_t)(wn * 64 + nb2 * 16 + brow) * 128 + ks * 32 + bcol;
                ldm_x4(bf[nb2], bbase + sw128(off));
            }
#pragma unroll
            for (int mt = 0; mt < 2; mt++)
#pragma unroll
                for (int nb2 = 0; nb2 < 4; nb2++) {
                    mma_16816(acc[mt][nb2 * 2 + 0], a[mt], bf[nb2][0], bf[nb2][1]);
                    mma_16816(acc[mt][nb2 * 2 + 1], a[mt], bf[nb2][2], bf[nb2][3]);
                }
        }
    };

    // prologue: stages 0..STAGES-2
#pragma unroll
    for (int s = 0; s < STAGES - 1; s++) { load_chunk(s, s); cp_commit(); }

    for (int c = 0; c < NCH; c++) {
        cp_wait<STAGES - 2>();
        __syncthreads();
        if (c + STAGES - 1 < NCH) load_chunk(c + STAGES - 1, (c + STAGES - 1) % STAGES);
        cp_commit();
        compute_chunk(c % STAGES);
    }

    // epilogue: acc lane layout -> (row l/4 [+8], col 2(l%4) [+1])
    const float* Gb = GATE ? (Gate + (size_t)b * MTOT * NTOT) : nullptr;
    float* Db = D + (size_t)b * MTOT * NTOT;
    const int mrow = m0 + wm * 32 + (lid >> 2);
    const int ncol = n0 + wn * 64 + (lid & 3) * 2;
#pragma unroll
    for (int mt = 0; mt < 2; mt++) {
#pragma unroll
        for (int nb = 0; nb < 8; nb++) {
            const int r0 = mrow + mt * 16;
            const int cc = ncol + nb * 8;
            float2 v0 = make_float2(acc[mt][nb][0], acc[mt][nb][1]);
            float2 v1 = make_float2(acc[mt][nb][2], acc[mt][nb][3]);
            const size_t o0 = (size_t)r0 * NTOT + cc;
            const size_t o1 = (size_t)(r0 + 8) * NTOT + cc;
            if (GATE) {
                float2 g0 = *reinterpret_cast<const float2*>(Gb + o0);
                float2 g1 = *reinterpret_cast<const float2*>(Gb + o1);
                v0.x *= g0.x; v0.y *= g0.y; v1.x *= g1.x; v1.y *= g1.y;
            }
            *reinterpret_cast<float2*>(Db + o0) = v0;
            *reinterpret_cast<float2*>(Db + o1) = v1;
        }
    }
}

// ======================= prep kernels =======================
__global__ __launch_bounds__(256)
void split_kernel(const float* __restrict__ X, __nv_bfloat16* __restrict__ Hi,
                  __nv_bfloat16* __restrict__ Lo, size_t n)
{
    for (size_t i = (size_t)blockIdx.x * blockDim.x + threadIdx.x; i < n;
         i += (size_t)gridDim.x * blockDim.x) {
        float x = X[i];
        __nv_bfloat16 h = __float2bfloat16(x);
        Hi[i] = h;
        Lo[i] = __float2bfloat16(x - __bfloat162float(h));
    }
}

// Q prep: split Q (K-major for GEMM1 B) and transposed Qt (K-major for GEMM2 B)
__global__ __launch_bounds__(256)
void q_prep_kernel(const float* __restrict__ Q, __nv_bfloat16* __restrict__ Qhi,
                   __nv_bfloat16* __restrict__ Qlo, __nv_bfloat16* __restrict__ Thi,
                   __nv_bfloat16* __restrict__ Tlo)
{
    __shared__ float tile[32][33];
    const int b = blockIdx.z, d0 = blockIdx.x * 32, q0 = blockIdx.y * 32;
    const int tx = threadIdx.x, ty = threadIdx.y;
    const float* Qb = Q + (size_t)b * LQ * DIM;
#pragma unroll
    for (int i = ty; i < 32; i += 8) {
        float x = Qb[(size_t)(q0 + i) * DIM + d0 + tx];
        tile[i][tx] = x;
        __nv_bfloat16 h = __float2bfloat16(x);
        size_t o = (size_t)b * LQ * DIM + (size_t)(q0 + i) * DIM + d0 + tx;
        Qhi[o] = h;
        Qlo[o] = __float2bfloat16(x - __bfloat162float(h));
    }
    __syncthreads();
#pragma unroll
    for (int i = ty; i < 32; i += 8) {
        float x = tile[tx][i];
        __nv_bfloat16 h = __float2bfloat16(x);
        size_t o = (size_t)b * DIM * LQ + (size_t)(d0 + i) * LQ + q0 + tx;
        Thi[o] = h;
        Tlo[o] = __float2bfloat16(x - __bfloat162float(h));
    }
}

// softmax over contiguous rows of 512 + bf16 hi/lo split of alpha
__global__ __launch_bounds__(256)
void softmax_split_kernel(const float* __restrict__ S, __nv_bfloat16* __restrict__ Shi,
                          __nv_bfloat16* __restrict__ Slo)
{
    const int row  = blockIdx.x * 8 + (threadIdx.x >> 5);
    const int lane = threadIdx.x & 31;
    const float* p = S + (size_t)row * LQ;

    float v[16];
    float mx = -INFINITY;
#pragma unroll
    for (int i = 0; i < 16; i++) { v[i] = p[lane + i * 32]; mx = fmaxf(mx, v[i]); }
#pragma unroll
    for (int o = 16; o > 0; o >>= 1) mx = fmaxf(mx, __shfl_xor_sync(0xffffffffu, mx, o));
    float sum = 0.f;
#pragma unroll
    for (int i = 0; i < 16; i++) { v[i] = expf(v[i] - mx); sum += v[i]; }
#pragma unroll
    for (int o = 16; o > 0; o >>= 1) sum += __shfl_xor_sync(0xffffffffu, sum, o);
    const float inv = 1.f / sum;
#pragma unroll
    for (int i = 0; i < 16; i++) {
        float w = v[i] * inv;
        __nv_bfloat16 h = __float2bfloat16(w);
        const size_t o = (size_t)row * LQ + lane + i * 32;
        Shi[o] = h;
        Slo[o] = __float2bfloat16(w - __bfloat162float(h));
    }
}

// ======================= launch =======================
extern "C" void kernel_launch(void* const* d_in, const int* in_sizes, int n_in,
                              void* d_out, int out_size)
{
    const int ctx_elems = (int)CE;
    const float* ctx, * qry;
    if (in_sizes[0] == ctx_elems) { ctx = (const float*)d_in[0]; qry = (const float*)d_in[1]; }
    else                          { ctx = (const float*)d_in[1]; qry = (const float*)d_in[0]; }
    float* out = (float*)d_out;

    unsigned char* sc = nullptr;
    cudaGetSymbolAddress((void**)&sc, g_scratch);
    float*         S    = (float*)(sc + OFF_S);
    __nv_bfloat16* Chi  = (__nv_bfloat16*)(sc + OFF_CHI);
    __nv_bfloat16* Clo  = (__nv_bfloat16*)(sc + OFF_CLO);
    __nv_bfloat16* Qhi  = (__nv_bfloat16*)(sc + OFF_QHI);
    __nv_bfloat16* Qlo  = (__nv_bfloat16*)(sc + OFF_QLO);
    __nv_bfloat16* Qthi = (__nv_bfloat16*)(sc + OFF_QTHI);
    __nv_bfloat16* Qtlo = (__nv_bfloat16*)(sc + OFF_QTLO);
    __nv_bfloat16* Shi  = (__nv_bfloat16*)(sc + OFF_SHI);
    __nv_bfloat16* Slo  = (__nv_bfloat16*)(sc + OFF_SLO);

    cudaFuncSetAttribute(mm_hmma_kernel<DIM, LQ, LC, false>,
                         cudaFuncAttributeMaxDynamicSharedMemorySize, SMEM_DYN_BYTES);
    cudaFuncSetAttribute(mm_hmma_kernel<LQ, DIM, LC, true>,
                         cudaFuncAttributeMaxDynamicSharedMemorySize, SMEM_DYN_BYTES);

    // 1) split context into bf16 hi/lo
    split_kernel<<<2048, 256>>>(ctx, Chi, Clo, CE);
    // 2) split + transpose query
    {
        dim3 grid(DIM / 32, LQ / 32, BATCH);
        q_prep_kernel<<<grid, dim3(32, 8)>>>(qry, Qhi, Qlo, Qthi, Qtlo);
    }
    // 3) GEMM1 (HMMA): S[c,q] = C·Q^T via hi·hi + lo·hi + hi·lo
    {
        dim3 grid(LC / 128, LQ / 128, BATCH);
        mm_hmma_kernel<DIM, LQ, LC, false><<<grid, 256, SMEM_DYN_BYTES>>>(
            Chi, Clo, Chi, Qhi, Qhi, Qlo, nullptr, S);
    }
    // 4) softmax over q + split alpha
    softmax_split_kernel<<<BATCH * LC / 8, 256>>>(S, Shi, Slo);
    // 5) GEMM2 (HMMA) + gate: out[c,d] = ctx[c,d] * (alpha·Qt^T)
    {
        dim3 grid(LC / 128, DIM / 128, BATCH);
        mm_hmma_kernel<LQ, DIM, LC, true><<<grid, 256, SMEM_DYN_BYTES>>>(
            Shi, Slo, Shi, Qthi, Qthi, Qtlo, ctx, out);
    }
    (void)n_in; (void)out_size;
}

// round 14
// speedup vs baseline: 2.3007x; 1.0223x over previous
#include <cuda_runtime.h>
#include <cuda_bf16.h>
#include <math.h>
#include <stdint.h>

#define BATCH 8
#define LC    2048
#define LQ    512
#define DIM   768

static constexpr size_t CE = (size_t)BATCH * LC * DIM;   // 12,582,912
static constexpr size_t QE = (size_t)BATCH * LQ * DIM;   //  3,145,728
static constexpr size_t SE = (size_t)BATCH * LC * LQ;    //  8,388,608

// ---- scratch layout (single __device__ blob; no allocation allowed) ----
static constexpr size_t OFF_S    = 0;                    // fp32 logits [B][LC][LQ]
static constexpr size_t OFF_CHI  = OFF_S   + SE * 4;
static constexpr size_t OFF_CLO  = OFF_CHI + CE * 2;
static constexpr size_t OFF_QHI  = OFF_CLO + CE * 2;
static constexpr size_t OFF_QLO  = OFF_QHI + QE * 2;
static constexpr size_t OFF_QTHI = OFF_QLO + QE * 2;     // Q transposed [B][DIM][LQ]
static constexpr size_t OFF_QTLO = OFF_QTHI + QE * 2;
static constexpr size_t OFF_SHI  = OFF_QTLO + QE * 2;    // softmax(alpha) split
static constexpr size_t OFF_SLO  = OFF_SHI + SE * 2;
static constexpr size_t SCRATCH_BYTES = OFF_SLO + SE * 2;

__device__ __align__(1024) unsigned char g_scratch[SCRATCH_BYTES];

// ======================= helpers (all plain sm_80+ PTX, no 'a' features) ===
__device__ __forceinline__ uint32_t smem_u32(const void* p) {
    uint32_t a;
    asm("{ .reg .u64 t; cvta.to.shared.u64 t, %1; cvt.u32.u64 %0, t; }" : "=r"(a) : "l"(p));
    return a;
}
__device__ __forceinline__ void cp_async16(uint32_t dst, const void* src) {
    asm volatile("cp.async.cg.shared.global [%0], [%1], 16;" :: "r"(dst), "l"(src) : "memory");
}
__device__ __forceinline__ void cp_commit() {
    asm volatile("cp.async.commit_group;" ::: "memory");
}
template <int N>
__device__ __forceinline__ void cp_wait() {
    asm volatile("cp.async.wait_group %0;" :: "n"(N) : "memory");
}
__device__ __forceinline__ void ldm_x4(uint32_t (&r)[4], uint32_t addr) {
    asm volatile("ldmatrix.sync.aligned.m8n8.x4.shared.b16 {%0,%1,%2,%3}, [%4];"
                 : "=r"(r[0]), "=r"(r[1]), "=r"(r[2]), "=r"(r[3]) : "r"(addr));
}
__device__ __forceinline__ void mma_16816(float (&c)[4], const uint32_t (&a)[4],
                                          uint32_t b0, uint32_t b1) {
    asm volatile("mma.sync.aligned.m16n8k16.row.col.f32.bf16.bf16.f32 "
                 "{%0,%1,%2,%3}, {%4,%5,%6,%7}, {%8,%9}, {%0,%1,%2,%3};"
                 : "+f"(c[0]), "+f"(c[1]), "+f"(c[2]), "+f"(c[3])
                 : "r"(a[0]), "r"(a[1]), "r"(a[2]), "r"(a[3]), "r"(b0), "r"(b1));
}
__device__ __forceinline__ uint32_t sw128(uint32_t off) {
    return off ^ ((off >> 3) & 0x70);   // Swizzle<3,4,3>: bits[6:4] ^= bits[9:7]
}

// ======================= HMMA GEMM (3-phase bf16 split) ====================
// D[M,N] = sum over phases p: Aph[p][M,K] (K-major) * Bph[p][N,K]^T (K-major)
// CTA tile 128x128, K-chunk 64 bf16 (128B rows, SW128), 3-stage cp.async.
static constexpr int STAGES = 3;
static constexpr int STAGE_BYTES = 32768;                 // A 16KB + B 16KB
static constexpr int SMEM_DYN_BYTES = STAGES * STAGE_BYTES;

template <int KDIM, int NTOT, int MTOT, bool GATE>
__global__ __launch_bounds__(256, 2)   // force <=128 regs: 2 CTAs/SM resident
void mm_hmma_kernel(const __nv_bfloat16* __restrict__ A0, const __nv_bfloat16* __restrict__ A1,
                    const __nv_bfloat16* __restrict__ A2, const __nv_bfloat16* __restrict__ B0,
                    const __nv_bfloat16* __restrict__ B1, const __nv_bfloat16* __restrict__ B2,
                    const float* __restrict__ Gate, float* __restrict__ D)
{
    constexpr int CPP = KDIM / 64;   // chunks per phase
    constexpr int NCH = 3 * CPP;     // total chunks

    extern __shared__ unsigned char sm[];

    const int t   = threadIdx.x;
    const int wid = t >> 5;
    const int lid = t & 31;
    const int wm  = wid >> 1;        // 0..3  (M warp row, 32 rows each)
    const int wn  = wid & 1;         // 0..1  (N warp col, 64 cols each)

    const int b  = blockIdx.z;
    const int m0 = blockIdx.x * 128;
    const int n0 = blockIdx.y * 128;

    const size_t bA = (size_t)b * MTOT * KDIM;
    const size_t bB = (size_t)b * NTOT * KDIM;
    const __nv_bfloat16* APh[3] = { A0 + bA, A1 + bA, A2 + bA };
    const __nv_bfloat16* BPh[3] = { B0 + bB, B1 + bB, B2 + bB };

    // cp.async mapping: thread t covers rows (t>>3)+32j, 16B col (t&7)
    const int lr  = t >> 3;          // 0..31
    const int lc16 = (t & 7);        // 0..7
    const uint32_t sm_base = smem_u32(sm);

    auto load_chunk = [&](int c, int stage) {
        const int p  = c / CPP;
        const int kk = (c % CPP) * 64;
        const __nv_bfloat16* Ap = APh[p];
        const __nv_bfloat16* Bp = BPh[p];
        const uint32_t abase = sm_base + stage * STAGE_BYTES;
        const uint32_t bbase = abase + 16384;
#pragma unroll
        for (int j = 0; j < 4; j++) {
            const int row = lr + j * 32;
            const uint32_t sw = sw128((uint32_t)row * 128 + (uint32_t)lc16 * 16);
            cp_async16(abase + sw, Ap + (size_t)(m0 + row) * KDIM + kk + lc16 * 8);
            cp_async16(bbase + sw, Bp + (size_t)(n0 + row) * KDIM + kk + lc16 * 8);
        }
    };

    float acc[2][8][4];
#pragma unroll
    for (int i = 0; i < 2; i++)
#pragma unroll
        for (int j = 0; j < 8; j++)
#pragma unroll
            for (int k = 0; k < 4; k++) acc[i][j][k] = 0.f;

    // ldmatrix per-lane row/col (within a 16-row, 32-byte k-step window)
    const int arow = (lid & 7) + 8 * ((lid >> 3) & 1);   // A: m within 16
    const int acol = ((lid >> 4) & 1) * 16;              // A: k byte 0/16
    const int brow = (lid & 7) + 8 * ((lid >> 4) & 1);   // B: n within 16
    const int bcol = ((lid >> 3) & 1) * 16;              // B: k byte 0/16

    auto compute_chunk = [&](int stage) {
        const uint32_t abase = sm_base + stage * STAGE_BYTES;
        const uint32_t bbase = abase + 16384;
#pragma unroll
        for (int ks = 0; ks < 4; ks++) {
            uint32_t a[2][4];
#pragma unroll
            for (int mt = 0; mt < 2; mt++) {
                uint32_t off = (uint32_t)(wm * 32 + mt * 16 + arow) * 128 + ks * 32 + acol;
                ldm_x4(a[mt], abase + sw128(off));
            }
            uint32_t bf[4][4];
#pragma unroll
            for (int nb2 = 0; nb2 < 4; nb2++) {
                uint32_t off = (uint32_t)(wn * 64 + nb2 * 16 + brow) * 128 + ks * 32 + bcol;
                ldm_x4(bf[nb2], bbase + sw128(off));
            }
#pragma unroll
            for (int mt = 0; mt < 2; mt++)
#pragma unroll
                for (int nb2 = 0; nb2 < 4; nb2++) {
                    mma_16816(acc[mt][nb2 * 2 + 0], a[mt], bf[nb2][0], bf[nb2][1]);
                    mma_16816(acc[mt][nb2 * 2 + 1], a[mt], bf[nb2][2], bf[nb2][3]);
                }
        }
    };

    // prologue: stages 0..STAGES-2
#pragma unroll
    for (int s = 0; s < STAGES - 1; s++) { load_chunk(s, s); cp_commit(); }

    for (int c = 0; c < NCH; c++) {
        cp_wait<STAGES - 2>();
        __syncthreads();
        if (c + STAGES - 1 < NCH) load_chunk(c + STAGES - 1, (c + STAGES - 1) % STAGES);
        cp_commit();
        compute_chunk(c % STAGES);
    }

    // epilogue: acc lane layout -> (row l/4 [+8], col 2(l%4) [+1])
    const float* Gb = GATE ? (Gate + (size_t)b * MTOT * NTOT) : nullptr;
    float* Db = D + (size_t)b * MTOT * NTOT;
    const int mrow = m0 + wm * 32 + (lid >> 2);
    const int ncol = n0 + wn * 64 + (lid & 3) * 2;
#pragma unroll
    for (int mt = 0; mt < 2; mt++) {
#pragma unroll
        for (int nb = 0; nb < 8; nb++) {
            const int r0 = mrow + mt * 16;
            const int cc = ncol + nb * 8;
            float2 v0 = make_float2(acc[mt][nb][0], acc[mt][nb][1]);
            float2 v1 = make_float2(acc[mt][nb][2], acc[mt][nb][3]);
            const size_t o0 = (size_t)r0 * NTOT + cc;
            const size_t o1 = (size_t)(r0 + 8) * NTOT + cc;
            if (GATE) {
                float2 g0 = *reinterpret_cast<const float2*>(Gb + o0);
                float2 g1 = *reinterpret_cast<const float2*>(Gb + o1);
                v0.x *= g0.x; v0.y *= g0.y; v1.x *= g1.x; v1.y *= g1.y;
            }
            *reinterpret_cast<float2*>(Db + o0) = v0;
            *reinterpret_cast<float2*>(Db + o1) = v1;
        }
    }
}

// ======================= prep kernels =======================
// vectorized: 2 elems/thread, packed bf16x2 stores
__global__ __launch_bounds__(256)
void split_kernel(const float* __restrict__ X, __nv_bfloat16* __restrict__ Hi,
                  __nv_bfloat16* __restrict__ Lo, size_t n2)
{
    const float2* X2 = reinterpret_cast<const float2*>(X);
    __nv_bfloat162* H2 = reinterpret_cast<__nv_bfloat162*>(Hi);
    __nv_bfloat162* L2 = reinterpret_cast<__nv_bfloat162*>(Lo);
    for (size_t i = (size_t)blockIdx.x * blockDim.x + threadIdx.x; i < n2;
         i += (size_t)gridDim.x * blockDim.x) {
        float2 x = X2[i];
        __nv_bfloat16 h0 = __float2bfloat16(x.x);
        __nv_bfloat16 h1 = __float2bfloat16(x.y);
        H2[i] = __nv_bfloat162(h0, h1);
        L2[i] = __nv_bfloat162(__float2bfloat16(x.x - __bfloat162float(h0)),
                               __float2bfloat16(x.y - __bfloat162float(h1)));
    }
}

// Q prep: split Q (K-major for GEMM1 B) and transposed Qt (K-major for GEMM2 B)
__global__ __launch_bounds__(256)
void q_prep_kernel(const float* __restrict__ Q, __nv_bfloat16* __restrict__ Qhi,
                   __nv_bfloat16* __restrict__ Qlo, __nv_bfloat16* __restrict__ Thi,
                   __nv_bfloat16* __restrict__ Tlo)
{
    __shared__ float tile[32][33];
    const int b = blockIdx.z, d0 = blockIdx.x * 32, q0 = blockIdx.y * 32;
    const int tx = threadIdx.x, ty = threadIdx.y;
    const float* Qb = Q + (size_t)b * LQ * DIM;
#pragma unroll
    for (int i = ty; i < 32; i += 8) {
        float x = Qb[(size_t)(q0 + i) * DIM + d0 + tx];
        tile[i][tx] = x;
        __nv_bfloat16 h = __float2bfloat16(x);
        size_t o = (size_t)b * LQ * DIM + (size_t)(q0 + i) * DIM + d0 + tx;
        Qhi[o] = h;
        Qlo[o] = __float2bfloat16(x - __bfloat162float(h));
    }
    __syncthreads();
#pragma unroll
    for (int i = ty; i < 32; i += 8) {
        float x = tile[tx][i];
        __nv_bfloat16 h = __float2bfloat16(x);
        size_t o = (size_t)b * DIM * LQ + (size_t)(d0 + i) * LQ + q0 + tx;
        Thi[o] = h;
        Tlo[o] = __float2bfloat16(x - __bfloat162float(h));
    }
}

// softmax over contiguous rows of 512 + bf16 hi/lo split of alpha (vectorized)
__global__ __launch_bounds__(256)
void softmax_split_kernel(const float* __restrict__ S, __nv_bfloat16* __restrict__ Shi,
                          __nv_bfloat16* __restrict__ Slo)
{
    const int row  = blockIdx.x * 8 + (threadIdx.x >> 5);
    const int lane = threadIdx.x & 31;
    const float2* p2 = reinterpret_cast<const float2*>(S + (size_t)row * LQ);
    __nv_bfloat162* h2 = reinterpret_cast<__nv_bfloat162*>(Shi + (size_t)row * LQ);
    __nv_bfloat162* l2 = reinterpret_cast<__nv_bfloat162*>(Slo + (size_t)row * LQ);

    float2 v[8];
    float mx = -INFINITY;
#pragma unroll
    for (int i = 0; i < 8; i++) {
        v[i] = p2[lane + i * 32];
        mx = fmaxf(mx, fmaxf(v[i].x, v[i].y));
    }
#pragma unroll
    for (int o = 16; o > 0; o >>= 1) mx = fmaxf(mx, __shfl_xor_sync(0xffffffffu, mx, o));
    float sum = 0.f;
#pragma unroll
    for (int i = 0; i < 8; i++) {
        v[i].x = expf(v[i].x - mx);
        v[i].y = expf(v[i].y - mx);
        sum += v[i].x + v[i].y;
    }
#pragma unroll
    for (int o = 16; o > 0; o >>= 1) sum += __shfl_xor_sync(0xffffffffu, sum, o);
    const float inv = 1.f / sum;
#pragma unroll
    for (int i = 0; i < 8; i++) {
        float w0 = v[i].x * inv, w1 = v[i].y * inv;
        __nv_bfloat16 a0 = __float2bfloat16(w0);
        __nv_bfloat16 a1 = __float2bfloat16(w1);
        h2[lane + i * 32] = __nv_bfloat162(a0, a1);
        l2[lane + i * 32] = __nv_bfloat162(__float2bfloat16(w0 - __bfloat162float(a0)),
                                           __float2bfloat16(w1 - __bfloat162float(a1)));
    }
}

// ======================= launch =======================
extern "C" void kernel_launch(void* const* d_in, const int* in_sizes, int n_in,
                              void* d_out, int out_size)
{
    const int ctx_elems = (int)CE;
    const float* ctx, * qry;
    if (in_sizes[0] == ctx_elems) { ctx = (const float*)d_in[0]; qry = (const float*)d_in[1]; }
    else                          { ctx = (const float*)d_in[1]; qry = (const float*)d_in[0]; }
    float* out = (float*)d_out;

    unsigned char* sc = nullptr;
    cudaGetSymbolAddress((void**)&sc, g_scratch);
    float*         S    = (float*)(sc + OFF_S);
    __nv_bfloat16* Chi  = (__nv_bfloat16*)(sc + OFF_CHI);
    __nv_bfloat16* Clo  = (__nv_bfloat16*)(sc + OFF_CLO);
    __nv_bfloat16* Qhi  = (__nv_bfloat16*)(sc + OFF_QHI);
    __nv_bfloat16* Qlo  = (__nv_bfloat16*)(sc + OFF_QLO);
    __nv_bfloat16* Qthi = (__nv_bfloat16*)(sc + OFF_QTHI);
    __nv_bfloat16* Qtlo = (__nv_bfloat16*)(sc + OFF_QTLO);
    __nv_bfloat16* Shi  = (__nv_bfloat16*)(sc + OFF_SHI);
    __nv_bfloat16* Slo  = (__nv_bfloat16*)(sc + OFF_SLO);

    cudaFuncSetAttribute(mm_hmma_kernel<DIM, LQ, LC, false>,
                         cudaFuncAttributeMaxDynamicSharedMemorySize, SMEM_DYN_BYTES);
    cudaFuncSetAttribute(mm_hmma_kernel<LQ, DIM, LC, true>,
                         cudaFuncAttributeMaxDynamicSharedMemorySize, SMEM_DYN_BYTES);

    // 1) split context into bf16 hi/lo
    split_kernel<<<1776, 256>>>(ctx, Chi, Clo, CE / 2);
    // 2) split + transpose query
    {
        dim3 grid(DIM / 32, LQ / 32, BATCH);
        q_prep_kernel<<<grid, dim3(32, 8)>>>(qry, Qhi, Qlo, Qthi, Qtlo);
    }
    // 3) GEMM1 (HMMA): S[c,q] = C·Q^T via hi·hi + lo·hi + hi·lo
    {
        dim3 grid(LC / 128, LQ / 128, BATCH);
        mm_hmma_kernel<DIM, LQ, LC, false><<<grid, 256, SMEM_DYN_BYTES>>>(
            Chi, Clo, Chi, Qhi, Qhi, Qlo, nullptr, S);
    }
    // 4) softmax over q + split alpha
    softmax_split_kernel<<<BATCH * LC / 8, 256>>>(S, Shi, Slo);
    // 5) GEMM2 (HMMA) + gate: out[c,d] = ctx[c,d] * (alpha·Qt^T)
    {
        dim3 grid(LC / 128, DIM / 128, BATCH);
        mm_hmma_kernel<LQ, DIM, LC, true><<<grid, 256, SMEM_DYN_BYTES>>>(
            Shi, Slo, Shi, Qthi, Qthi, Qtlo, ctx, out);
    }
    (void)n_in; (void)out_size;
}